// round 11
// baseline (speedup 1.0000x reference)
#include <cuda_runtime.h>
#include <cstdint>

// MultiHeadAttention: B=4, T=2048, C=1024, H=16, D=64
// R10: R5 structure with the tile-staging trip-count bug fixed (2 -> 8 iters,
//      now written symbolically). 3xTF32 pipelined GEMMs + 3xTF32 TC flash attn.

#define B_ 4
#define T_ 2048
#define C_ 1024
#define H_ 16
#define D_ 64
#define M_ (B_ * T_)          // 8192
#define C3_ (3 * C_)          // 3072

// Scratch (allocation-free rule: __device__ globals)
__device__ float g_qkv[M_ * C3_];   // ~100.7 MB
__device__ float g_att[M_ * C_];    // ~33.6 MB

// ---------------------------------------------------------------------------
// tf32 helpers
// ---------------------------------------------------------------------------
__device__ __forceinline__ void split_tf32(float x, uint32_t& h, uint32_t& l) {
    uint32_t hi;
    asm("cvt.rna.tf32.f32 %0, %1;" : "=r"(hi) : "f"(x));
    float r = x - __uint_as_float(hi);
    uint32_t lo;
    asm("cvt.rna.tf32.f32 %0, %1;" : "=r"(lo) : "f"(r));
    h = hi; l = lo;
}

__device__ __forceinline__ void mma_tf32(float c[4],
                                         uint32_t a0, uint32_t a1, uint32_t a2, uint32_t a3,
                                         uint32_t b0, uint32_t b1) {
    asm volatile(
        "mma.sync.aligned.m16n8k8.row.col.f32.tf32.tf32.f32 "
        "{%0,%1,%2,%3}, {%4,%5,%6,%7}, {%8,%9}, {%0,%1,%2,%3};\n"
        : "+f"(c[0]), "+f"(c[1]), "+f"(c[2]), "+f"(c[3])
        : "r"(a0), "r"(a1), "r"(a2), "r"(a3), "r"(b0), "r"(b1));
}

// ---------------------------------------------------------------------------
// 3xTF32 tensor-core GEMM with register-prefetch: A[MxK] * B[KxN] -> C (+bias)
// CTA: 128x128x16, 256 threads = 8 warps (2x4), warp tile 64x32 (4x4 mma grid).
// ---------------------------------------------------------------------------
__global__ __launch_bounds__(256) void gemm_tf32x3(
    const float* __restrict__ A, const float* __restrict__ Bm,
    float* __restrict__ Cm, const float* __restrict__ bias,
    int M, int N, int K)
{
    constexpr int BM = 128, BN = 128, BK = 16;
    constexpr int AST = BK + 4;     // 20 floats per A row
    constexpr int BST = BN + 8;     // 136 floats per B row

    __shared__ float Ah[BM][AST], Al[BM][AST];
    __shared__ float Bh[BK][BST], Bl[BK][BST];

    const int tid  = threadIdx.x;
    const int wid  = tid >> 5;
    const int lane = tid & 31;
    const int wm   = wid >> 2;      // 0..1 -> 64-row band
    const int wn   = wid & 3;       // 0..3 -> 32-col band
    const int gr   = lane >> 2;     // 0..7
    const int tg   = lane & 3;      // 0..3

    const int bx = blockIdx.x, by = blockIdx.y;
    const float* Ab = A  + (size_t)by * BM * K;
    const float* Bb = Bm + (size_t)bx * BN;

    const int aRow = tid >> 2;          // 0..63 (and +64)
    const int aCol = (tid & 3) * 4;     // 0,4,8,12
    const int bRow = tid >> 5;          // 0..7 (and +8)
    const int bCol = (tid & 31) * 4;    // 0..124

    const float* aPtr0 = Ab + (size_t)aRow * K + aCol;
    const float* aPtr1 = Ab + (size_t)(aRow + 64) * K + aCol;
    const float* bPtr0 = Bb + (size_t)bRow * N + bCol;
    const float* bPtr1 = Bb + (size_t)(bRow + 8) * N + bCol;

    float acc[4][4][4];
    #pragma unroll
    for (int i = 0; i < 4; i++)
        #pragma unroll
        for (int j = 0; j < 4; j++)
            #pragma unroll
            for (int r = 0; r < 4; r++) acc[i][j][r] = 0.f;

    // prefetch tile 0
    float4 pa0 = *(const float4*)(aPtr0);
    float4 pa1 = *(const float4*)(aPtr1);
    float4 pb0 = *(const float4*)(bPtr0);
    float4 pb1 = *(const float4*)(bPtr1);

    for (int k0 = 0; k0 < K; k0 += BK) {
        // --- split + store prefetched tile into smem ---
        {
            uint32_t h, l;
            float4 hv, lv;
            split_tf32(pa0.x, h, l); hv.x = __uint_as_float(h); lv.x = __uint_as_float(l);
            split_tf32(pa0.y, h, l); hv.y = __uint_as_float(h); lv.y = __uint_as_float(l);
            split_tf32(pa0.z, h, l); hv.z = __uint_as_float(h); lv.z = __uint_as_float(l);
            split_tf32(pa0.w, h, l); hv.w = __uint_as_float(h); lv.w = __uint_as_float(l);
            *(float4*)&Ah[aRow][aCol] = hv;
            *(float4*)&Al[aRow][aCol] = lv;
            split_tf32(pa1.x, h, l); hv.x = __uint_as_float(h); lv.x = __uint_as_float(l);
            split_tf32(pa1.y, h, l); hv.y = __uint_as_float(h); lv.y = __uint_as_float(l);
            split_tf32(pa1.z, h, l); hv.z = __uint_as_float(h); lv.z = __uint_as_float(l);
            split_tf32(pa1.w, h, l); hv.w = __uint_as_float(h); lv.w = __uint_as_float(l);
            *(float4*)&Ah[aRow + 64][aCol] = hv;
            *(float4*)&Al[aRow + 64][aCol] = lv;
            split_tf32(pb0.x, h, l); hv.x = __uint_as_float(h); lv.x = __uint_as_float(l);
            split_tf32(pb0.y, h, l); hv.y = __uint_as_float(h); lv.y = __uint_as_float(l);
            split_tf32(pb0.z, h, l); hv.z = __uint_as_float(h); lv.z = __uint_as_float(l);
            split_tf32(pb0.w, h, l); hv.w = __uint_as_float(h); lv.w = __uint_as_float(l);
            *(float4*)&Bh[bRow][bCol] = hv;
            *(float4*)&Bl[bRow][bCol] = lv;
            split_tf32(pb1.x, h, l); hv.x = __uint_as_float(h); lv.x = __uint_as_float(l);
            split_tf32(pb1.y, h, l); hv.y = __uint_as_float(h); lv.y = __uint_as_float(l);
            split_tf32(pb1.z, h, l); hv.z = __uint_as_float(h); lv.z = __uint_as_float(l);
            split_tf32(pb1.w, h, l); hv.w = __uint_as_float(h); lv.w = __uint_as_float(l);
            *(float4*)&Bh[bRow + 8][bCol] = hv;
            *(float4*)&Bl[bRow + 8][bCol] = lv;
        }
        __syncthreads();

        // --- issue next tile's gmem loads (overlap with mma below) ---
        if (k0 + BK < K) {
            pa0 = *(const float4*)(aPtr0 + k0 + BK);
            pa1 = *(const float4*)(aPtr1 + k0 + BK);
            pb0 = *(const float4*)(bPtr0 + (size_t)(k0 + BK) * N);
            pb1 = *(const float4*)(bPtr1 + (size_t)(k0 + BK) * N);
        }

        #pragma unroll
        for (int s = 0; s < 2; s++) {           // two k8 substeps per BK=16
            const int ks = s * 8;
            uint32_t ah[4][4], al_[4][4];
            #pragma unroll
            for (int mi = 0; mi < 4; mi++) {
                const int m = wm * 64 + mi * 16 + gr;
                const int k = ks + tg;
                ah[mi][0]  = __float_as_uint(Ah[m    ][k    ]);
                ah[mi][1]  = __float_as_uint(Ah[m + 8][k    ]);
                ah[mi][2]  = __float_as_uint(Ah[m    ][k + 4]);
                ah[mi][3]  = __float_as_uint(Ah[m + 8][k + 4]);
                al_[mi][0] = __float_as_uint(Al[m    ][k    ]);
                al_[mi][1] = __float_as_uint(Al[m + 8][k    ]);
                al_[mi][2] = __float_as_uint(Al[m    ][k + 4]);
                al_[mi][3] = __float_as_uint(Al[m + 8][k + 4]);
            }
            #pragma unroll
            for (int ni = 0; ni < 4; ni++) {
                const int n  = wn * 32 + ni * 8 + gr;
                const int kb = ks + tg;
                uint32_t bh0 = __float_as_uint(Bh[kb    ][n]);
                uint32_t bh1 = __float_as_uint(Bh[kb + 4][n]);
                uint32_t bl0 = __float_as_uint(Bl[kb    ][n]);
                uint32_t bl1 = __float_as_uint(Bl[kb + 4][n]);
                #pragma unroll
                for (int mi = 0; mi < 4; mi++) {
                    mma_tf32(acc[mi][ni], ah[mi][0], ah[mi][1], ah[mi][2], ah[mi][3], bl0, bl1);
                    mma_tf32(acc[mi][ni], al_[mi][0], al_[mi][1], al_[mi][2], al_[mi][3], bh0, bh1);
                    mma_tf32(acc[mi][ni], ah[mi][0], ah[mi][1], ah[mi][2], ah[mi][3], bh0, bh1);
                }
            }
        }
        __syncthreads();
    }

    #pragma unroll
    for (int mi = 0; mi < 4; mi++) {
        const int row0 = by * BM + wm * 64 + mi * 16 + gr;
        #pragma unroll
        for (int ni = 0; ni < 4; ni++) {
            const int col = bx * BN + wn * 32 + ni * 8 + tg * 2;
            float bx0 = 0.f, bx1 = 0.f;
            if (bias != nullptr) { bx0 = bias[col]; bx1 = bias[col + 1]; }
            float2 v0 = make_float2(acc[mi][ni][0] + bx0, acc[mi][ni][1] + bx1);
            float2 v1 = make_float2(acc[mi][ni][2] + bx0, acc[mi][ni][3] + bx1);
            *(float2*)(Cm + (size_t)row0 * N + col)       = v0;
            *(float2*)(Cm + (size_t)(row0 + 8) * N + col) = v1;
        }
    }
}

// ---------------------------------------------------------------------------
// Tensor-core flash attention (3xTF32), causal.
// Grid: (T/64, H, B), 128 threads = 4 warps; warp w owns q rows [w*16, w*16+16).
// KV tiles of 64 keys. S frag -> online softmax -> quad-shuffle P -> PV mma.
// ---------------------------------------------------------------------------
__global__ __launch_bounds__(128, 2) void flash_attn_tc(
    const float* __restrict__ qkv, float* __restrict__ out)
{
    constexpr int BKV = 64;   // kv rows per tile
    constexpr int KST = 68;   // K smem stride
    constexpr int VST = 72;   // V smem stride
    // tile staging: BKV rows x (D_/4) float4 vectors, 128 threads
    constexpr int NVEC  = BKV * (D_ / 4);        // 1024
    constexpr int NITER = NVEC / 128;            // 8  (the R5 bug: was 2)

    __shared__ float Ks[BKV][KST];
    __shared__ float Vs[BKV][VST];

    const int tid  = threadIdx.x;
    const int wid  = tid >> 5;
    const int lane = tid & 31;
    const int gr   = lane >> 2;     // 0..7
    const int tg   = lane & 3;      // 0..3

    const int qi = (int)gridDim.x - 1 - (int)blockIdx.x;  // reverse: big CTAs first
    const int h  = blockIdx.y;
    const int b  = blockIdx.z;
    const int q0 = qi * 64;

    const int base  = (b * T_) * C3_ + h * D_;
    const int kbase = base + C_;
    const int vbase = base + 2 * C_;

    // ---- stage Q tile (64x64) into Ks, scaled by 1/sqrt(D)=0.125 (exact) ----
    #pragma unroll
    for (int it = 0; it < NITER; it++) {
        int idx = it * 128 + tid;
        int r = idx >> 4;                 // D_/4 = 16 float4 per row
        int c = (idx & 15) * 4;
        float4 v = *(const float4*)(qkv + base + (size_t)(q0 + r) * C3_ + c);
        v.x *= 0.125f; v.y *= 0.125f; v.z *= 0.125f; v.w *= 0.125f;
        *(float4*)&Ks[r][c] = v;
    }
    __syncthreads();

    // ---- extract Q fragments (hi/lo) into registers ----
    const int qrow = wid * 16 + gr;
    uint32_t qh[8][4], ql[8][4];
    #pragma unroll
    for (int kt = 0; kt < 8; kt++) {
        float f0 = Ks[qrow    ][kt * 8 + tg];
        float f1 = Ks[qrow + 8][kt * 8 + tg];
        float f2 = Ks[qrow    ][kt * 8 + tg + 4];
        float f3 = Ks[qrow + 8][kt * 8 + tg + 4];
        split_tf32(f0, qh[kt][0], ql[kt][0]);
        split_tf32(f1, qh[kt][1], ql[kt][1]);
        split_tf32(f2, qh[kt][2], ql[kt][2]);
        split_tf32(f3, qh[kt][3], ql[kt][3]);
    }
    __syncthreads();

    float o[8][4];
    #pragma unroll
    for (int nt = 0; nt < 8; nt++)
        #pragma unroll
        for (int r = 0; r < 4; r++) o[nt][r] = 0.f;
    float m0 = -1e30f, m1 = -1e30f;   // row maxima (rows qrow, qrow+8)
    float l0 = 0.f,    l1 = 0.f;      // per-thread partial row sums

    for (int j0 = 0; j0 <= q0; j0 += BKV) {
        // ---- load K,V tiles (raw fp32) ----
        #pragma unroll
        for (int it = 0; it < NITER; it++) {
            int idx = it * 128 + tid;
            int r = idx >> 4;
            int c = (idx & 15) * 4;
            size_t tok = (size_t)(j0 + r) * C3_;
            *(float4*)&Ks[r][c] = *(const float4*)(qkv + kbase + tok + c);
            *(float4*)&Vs[r][c] = *(const float4*)(qkv + vbase + tok + c);
        }
        __syncthreads();

        // ---- S = Q K^T  (16 x 64 per warp), 3xTF32 ----
        float s[8][4];
        #pragma unroll
        for (int nt = 0; nt < 8; nt++) {
            #pragma unroll
            for (int r = 0; r < 4; r++) s[nt][r] = 0.f;
            #pragma unroll
            for (int ks = 0; ks < 8; ks++) {
                float b0f = Ks[nt * 8 + gr][ks * 8 + tg];
                float b1f = Ks[nt * 8 + gr][ks * 8 + tg + 4];
                uint32_t bh0, bl0, bh1, bl1;
                split_tf32(b0f, bh0, bl0);
                split_tf32(b1f, bh1, bl1);
                mma_tf32(s[nt], qh[ks][0], qh[ks][1], qh[ks][2], qh[ks][3], bl0, bl1);
                mma_tf32(s[nt], ql[ks][0], ql[ks][1], ql[ks][2], ql[ks][3], bh0, bh1);
                mma_tf32(s[nt], qh[ks][0], qh[ks][1], qh[ks][2], qh[ks][3], bh0, bh1);
            }
        }

        // ---- causal mask (diagonal tile only: j0 == q0) ----
        if (j0 + BKV > q0) {
            const int row0 = q0 + qrow;
            const int row1 = row0 + 8;
            #pragma unroll
            for (int nt = 0; nt < 8; nt++) {
                const int col = j0 + nt * 8 + 2 * tg;
                if (col     > row0) s[nt][0] = -1e30f;
                if (col + 1 > row0) s[nt][1] = -1e30f;
                if (col     > row1) s[nt][2] = -1e30f;
                if (col + 1 > row1) s[nt][3] = -1e30f;
            }
        }

        // ---- online softmax ----
        float t0 = -1e30f, t1 = -1e30f;
        #pragma unroll
        for (int nt = 0; nt < 8; nt++) {
            t0 = fmaxf(t0, fmaxf(s[nt][0], s[nt][1]));
            t1 = fmaxf(t1, fmaxf(s[nt][2], s[nt][3]));
        }
        t0 = fmaxf(t0, __shfl_xor_sync(0xffffffffu, t0, 1));
        t0 = fmaxf(t0, __shfl_xor_sync(0xffffffffu, t0, 2));
        t1 = fmaxf(t1, __shfl_xor_sync(0xffffffffu, t1, 1));
        t1 = fmaxf(t1, __shfl_xor_sync(0xffffffffu, t1, 2));
        const float nm0 = fmaxf(m0, t0);
        const float nm1 = fmaxf(m1, t1);
        const float cr0 = __expf(m0 - nm0);
        const float cr1 = __expf(m1 - nm1);
        m0 = nm0; m1 = nm1;
        l0 *= cr0; l1 *= cr1;
        #pragma unroll
        for (int nt = 0; nt < 8; nt++) {
            o[nt][0] *= cr0; o[nt][1] *= cr0;
            o[nt][2] *= cr1; o[nt][3] *= cr1;
        }
        #pragma unroll
        for (int nt = 0; nt < 8; nt++) {
            s[nt][0] = __expf(s[nt][0] - m0);
            s[nt][1] = __expf(s[nt][1] - m0);
            s[nt][2] = __expf(s[nt][2] - m1);
            s[nt][3] = __expf(s[nt][3] - m1);
            l0 += s[nt][0] + s[nt][1];
            l1 += s[nt][2] + s[nt][3];
        }

        // ---- O += P V : for each 8-key tile build P A-frag via quad shuffle ----
        #pragma unroll
        for (int kt = 0; kt < 8; kt++) {
            const int srcA = (lane & ~3) + (tg >> 1);
            const int srcB = srcA + 2;
            float v0 = __shfl_sync(0xffffffffu, s[kt][0], srcA);
            float v1 = __shfl_sync(0xffffffffu, s[kt][1], srcA);
            float v2 = __shfl_sync(0xffffffffu, s[kt][2], srcA);
            float v3 = __shfl_sync(0xffffffffu, s[kt][3], srcA);
            float w0 = __shfl_sync(0xffffffffu, s[kt][0], srcB);
            float w1 = __shfl_sync(0xffffffffu, s[kt][1], srcB);
            float w2 = __shfl_sync(0xffffffffu, s[kt][2], srcB);
            float w3 = __shfl_sync(0xffffffffu, s[kt][3], srcB);
            const bool odd = (tg & 1);
            float a0f = odd ? v1 : v0;   // P[gr   ][tg  ]
            float a1f = odd ? v3 : v2;   // P[gr+8 ][tg  ]
            float a2f = odd ? w1 : w0;   // P[gr   ][tg+4]
            float a3f = odd ? w3 : w2;   // P[gr+8 ][tg+4]
            uint32_t ah0, al0, ah1, al1, ah2, al2, ah3, al3;
            split_tf32(a0f, ah0, al0);
            split_tf32(a1f, ah1, al1);
            split_tf32(a2f, ah2, al2);
            split_tf32(a3f, ah3, al3);
            #pragma unroll
            for (int nt = 0; nt < 8; nt++) {
                float b0f = Vs[kt * 8 + tg    ][nt * 8 + gr];
                float b1f = Vs[kt * 8 + tg + 4][nt * 8 + gr];
                uint32_t bh0, bl0, bh1, bl1;
                split_tf32(b0f, bh0, bl0);
                split_tf32(b1f, bh1, bl1);
                mma_tf32(o[nt], ah0, ah1, ah2, ah3, bl0, bl1);
                mma_tf32(o[nt], al0, al1, al2, al3, bh0, bh1);
                mma_tf32(o[nt], ah0, ah1, ah2, ah3, bh0, bh1);
            }
        }
        __syncthreads();
    }

    // ---- finalize: reduce l across quad, normalize, write ----
    l0 += __shfl_xor_sync(0xffffffffu, l0, 1);
    l0 += __shfl_xor_sync(0xffffffffu, l0, 2);
    l1 += __shfl_xor_sync(0xffffffffu, l1, 1);
    l1 += __shfl_xor_sync(0xffffffffu, l1, 2);
    const float inv0 = 1.0f / l0;
    const float inv1 = 1.0f / l1;

    const size_t row0 = (size_t)(b * T_ + q0 + qrow);
    #pragma unroll
    for (int nt = 0; nt < 8; nt++) {
        const int col = h * D_ + nt * 8 + 2 * tg;
        *(float2*)(out + row0 * C_ + col)       = make_float2(o[nt][0] * inv0, o[nt][1] * inv0);
        *(float2*)(out + (row0 + 8) * C_ + col) = make_float2(o[nt][2] * inv1, o[nt][3] * inv1);
    }
}

// ---------------------------------------------------------------------------
extern "C" void kernel_launch(void* const* d_in, const int* in_sizes, int n_in,
                              void* d_out, int out_size)
{
    const float* x     = (const float*)d_in[0];   // [B,T,C]
    const float* w_qkv = (const float*)d_in[1];   // [C,3C]
    const float* w_out = (const float*)d_in[2];   // [C,C]
    const float* b_out = (const float*)d_in[3];   // [C]
    float* out = (float*)d_out;                   // [B,T,C]

    float* qkv = nullptr;
    float* att = nullptr;
    cudaGetSymbolAddress((void**)&qkv, g_qkv);
    cudaGetSymbolAddress((void**)&att, g_att);

    // 1) QKV projection: [8192,1024] @ [1024,3072]   (tensor pipe, 3xTF32)
    gemm_tf32x3<<<dim3(C3_ / 128, M_ / 128), 256>>>(x, w_qkv, qkv, nullptr, M_, C3_, C_);

    // 2) Causal flash attention (tensor pipe) -> [B,T,C]
    flash_attn_tc<<<dim3(T_ / 64, H_, B_), 128>>>(qkv, att);

    // 3) Output projection + bias: [8192,1024] @ [1024,1024]   (tensor pipe, 3xTF32)
    gemm_tf32x3<<<dim3(C_ / 128, M_ / 128), 256>>>(att, w_out, out, b_out, M_, C_, C_);
}

// round 14
// speedup vs baseline: 1.6430x; 1.6430x over previous
#include <cuda_runtime.h>
#include <cstdint>

// MultiHeadAttention: B=4, T=2048, C=1024, H=16, D=64
// R11: GEMM rebuilt: raw-fp32 double-buffered smem + cp.async pipeline,
//      tf32 hi/lo split moved to fragment-load time (halves smem + LDS).
//      Flash attention identical to R10 (verified correct).

#define B_ 4
#define T_ 2048
#define C_ 1024
#define H_ 16
#define D_ 64
#define M_ (B_ * T_)          // 8192
#define C3_ (3 * C_)          // 3072

// Scratch (allocation-free rule: __device__ globals)
__device__ float g_qkv[M_ * C3_];   // ~100.7 MB
__device__ float g_att[M_ * C_];    // ~33.6 MB

// ---------------------------------------------------------------------------
// tf32 helpers
// ---------------------------------------------------------------------------
__device__ __forceinline__ void split_tf32(float x, uint32_t& h, uint32_t& l) {
    uint32_t hi;
    asm("cvt.rna.tf32.f32 %0, %1;" : "=r"(hi) : "f"(x));
    float r = x - __uint_as_float(hi);
    uint32_t lo;
    asm("cvt.rna.tf32.f32 %0, %1;" : "=r"(lo) : "f"(r));
    h = hi; l = lo;
}

__device__ __forceinline__ void mma_tf32(float c[4],
                                         uint32_t a0, uint32_t a1, uint32_t a2, uint32_t a3,
                                         uint32_t b0, uint32_t b1) {
    asm volatile(
        "mma.sync.aligned.m16n8k8.row.col.f32.tf32.tf32.f32 "
        "{%0,%1,%2,%3}, {%4,%5,%6,%7}, {%8,%9}, {%0,%1,%2,%3};\n"
        : "+f"(c[0]), "+f"(c[1]), "+f"(c[2]), "+f"(c[3])
        : "r"(a0), "r"(a1), "r"(a2), "r"(a3), "r"(b0), "r"(b1));
}

__device__ __forceinline__ void cp16(void* smem_ptr, const void* gptr) {
    uint32_t s = (uint32_t)__cvta_generic_to_shared(smem_ptr);
    asm volatile("cp.async.cg.shared.global [%0], [%1], 16;\n" :: "r"(s), "l"(gptr));
}

// ---------------------------------------------------------------------------
// 3xTF32 tensor-core GEMM, cp.async double-buffered, split-at-frag-load.
// A[MxK] * B[KxN] -> C[MxN] (+bias). CTA 128x128x16, 256 thr = 8 warps (2x4),
// warp tile 64x32 (4x4 mma grid).
// Raw smem: A stride 20 -> frag banks (4*gr+tg... ) 20g+t all-distinct;
//           B stride 136 -> 8t+g all-distinct. Conflict-free.
// ---------------------------------------------------------------------------
__global__ __launch_bounds__(256) void gemm_tf32x3(
    const float* __restrict__ A, const float* __restrict__ Bm,
    float* __restrict__ Cm, const float* __restrict__ bias,
    int M, int N, int K)
{
    constexpr int BM = 128, BN = 128, BK = 16;
    constexpr int AST = BK + 4;     // 20 floats per A row
    constexpr int BST = BN + 8;     // 136 floats per B row

    __shared__ float Araw[2][BM][AST];   // 2*128*20*4  = 20.5 KB
    __shared__ float Braw[2][BK][BST];   // 2*16*136*4  = 17.4 KB

    const int tid  = threadIdx.x;
    const int wid  = tid >> 5;
    const int lane = tid & 31;
    const int wm   = wid >> 2;      // 0..1 -> 64-row band
    const int wn   = wid & 3;       // 0..3 -> 32-col band
    const int gr   = lane >> 2;     // 0..7
    const int tg   = lane & 3;      // 0..3

    const int bx = blockIdx.x, by = blockIdx.y;
    const float* Ab = A  + (size_t)by * BM * K;
    const float* Bb = Bm + (size_t)bx * BN;

    const int aRow = tid >> 2;          // 0..63 (and +64)
    const int aCol = (tid & 3) * 4;     // 0,4,8,12
    const int bRow = tid >> 5;          // 0..7 (and +8)
    const int bCol = (tid & 31) * 4;    // 0..124

    const float* aPtr0 = Ab + (size_t)aRow * K + aCol;
    const float* aPtr1 = Ab + (size_t)(aRow + 64) * K + aCol;
    const float* bPtr0 = Bb + (size_t)bRow * N + bCol;
    const float* bPtr1 = Bb + (size_t)(bRow + 8) * N + bCol;

    float acc[4][4][4];
    #pragma unroll
    for (int i = 0; i < 4; i++)
        #pragma unroll
        for (int j = 0; j < 4; j++)
            #pragma unroll
            for (int r = 0; r < 4; r++) acc[i][j][r] = 0.f;

    // prologue: stage tile 0 into buffer 0
    cp16(&Araw[0][aRow     ][aCol], aPtr0);
    cp16(&Araw[0][aRow + 64][aCol], aPtr1);
    cp16(&Braw[0][bRow     ][bCol], bPtr0);
    cp16(&Braw[0][bRow +  8][bCol], bPtr1);
    asm volatile("cp.async.commit_group;\n" ::: "memory");

    int buf = 0;
    for (int k0 = 0; k0 < K; k0 += BK) {
        // issue next tile into the other buffer, then drain current tile
        if (k0 + BK < K) {
            const int nb = buf ^ 1;
            const int kn = k0 + BK;
            cp16(&Araw[nb][aRow     ][aCol], aPtr0 + kn);
            cp16(&Araw[nb][aRow + 64][aCol], aPtr1 + kn);
            cp16(&Braw[nb][bRow     ][bCol], bPtr0 + (size_t)kn * N);
            cp16(&Braw[nb][bRow +  8][bCol], bPtr1 + (size_t)kn * N);
            asm volatile("cp.async.commit_group;\n" ::: "memory");
            asm volatile("cp.async.wait_group 1;\n" ::: "memory");
        } else {
            asm volatile("cp.async.wait_group 0;\n" ::: "memory");
        }
        __syncthreads();

        #pragma unroll
        for (int s = 0; s < 2; s++) {           // two k8 substeps per BK=16
            const int ks = s * 8;
            // A fragments: raw load + split (hi/lo from the same float)
            uint32_t ah[4][4], al_[4][4];
            #pragma unroll
            for (int mi = 0; mi < 4; mi++) {
                const int m = wm * 64 + mi * 16 + gr;
                const int k = ks + tg;
                float f0 = Araw[buf][m    ][k    ];
                float f1 = Araw[buf][m + 8][k    ];
                float f2 = Araw[buf][m    ][k + 4];
                float f3 = Araw[buf][m + 8][k + 4];
                split_tf32(f0, ah[mi][0], al_[mi][0]);
                split_tf32(f1, ah[mi][1], al_[mi][1]);
                split_tf32(f2, ah[mi][2], al_[mi][2]);
                split_tf32(f3, ah[mi][3], al_[mi][3]);
            }
            #pragma unroll
            for (int ni = 0; ni < 4; ni++) {
                const int n  = wn * 32 + ni * 8 + gr;
                const int kb = ks + tg;
                float b0f = Braw[buf][kb    ][n];
                float b1f = Braw[buf][kb + 4][n];
                uint32_t bh0, bl0, bh1, bl1;
                split_tf32(b0f, bh0, bl0);
                split_tf32(b1f, bh1, bl1);
                #pragma unroll
                for (int mi = 0; mi < 4; mi++) {
                    mma_tf32(acc[mi][ni], ah[mi][0], ah[mi][1], ah[mi][2], ah[mi][3], bl0, bl1);
                    mma_tf32(acc[mi][ni], al_[mi][0], al_[mi][1], al_[mi][2], al_[mi][3], bh0, bh1);
                    mma_tf32(acc[mi][ni], ah[mi][0], ah[mi][1], ah[mi][2], ah[mi][3], bh0, bh1);
                }
            }
        }
        __syncthreads();
        buf ^= 1;
    }

    #pragma unroll
    for (int mi = 0; mi < 4; mi++) {
        const int row0 = by * BM + wm * 64 + mi * 16 + gr;
        #pragma unroll
        for (int ni = 0; ni < 4; ni++) {
            const int col = bx * BN + wn * 32 + ni * 8 + tg * 2;
            float bx0 = 0.f, bx1 = 0.f;
            if (bias != nullptr) { bx0 = bias[col]; bx1 = bias[col + 1]; }
            float2 v0 = make_float2(acc[mi][ni][0] + bx0, acc[mi][ni][1] + bx1);
            float2 v1 = make_float2(acc[mi][ni][2] + bx0, acc[mi][ni][3] + bx1);
            *(float2*)(Cm + (size_t)row0 * N + col)       = v0;
            *(float2*)(Cm + (size_t)(row0 + 8) * N + col) = v1;
        }
    }
}

// ---------------------------------------------------------------------------
// Tensor-core flash attention (3xTF32), causal.  IDENTICAL to R10 (verified).
// Grid: (T/64, H, B), 128 threads = 4 warps; warp w owns q rows [w*16, w*16+16).
// ---------------------------------------------------------------------------
__global__ __launch_bounds__(128, 2) void flash_attn_tc(
    const float* __restrict__ qkv, float* __restrict__ out)
{
    constexpr int BKV = 64;   // kv rows per tile
    constexpr int KST = 68;   // K smem stride
    constexpr int VST = 72;   // V smem stride
    constexpr int NVEC  = BKV * (D_ / 4);        // 1024
    constexpr int NITER = NVEC / 128;            // 8

    __shared__ float Ks[BKV][KST];
    __shared__ float Vs[BKV][VST];

    const int tid  = threadIdx.x;
    const int wid  = tid >> 5;
    const int lane = tid & 31;
    const int gr   = lane >> 2;     // 0..7
    const int tg   = lane & 3;      // 0..3

    const int qi = (int)gridDim.x - 1 - (int)blockIdx.x;  // reverse: big CTAs first
    const int h  = blockIdx.y;
    const int b  = blockIdx.z;
    const int q0 = qi * 64;

    const int base  = (b * T_) * C3_ + h * D_;
    const int kbase = base + C_;
    const int vbase = base + 2 * C_;

    // ---- stage Q tile (64x64) into Ks, scaled by 1/sqrt(D)=0.125 (exact) ----
    #pragma unroll
    for (int it = 0; it < NITER; it++) {
        int idx = it * 128 + tid;
        int r = idx >> 4;                 // D_/4 = 16 float4 per row
        int c = (idx & 15) * 4;
        float4 v = *(const float4*)(qkv + base + (size_t)(q0 + r) * C3_ + c);
        v.x *= 0.125f; v.y *= 0.125f; v.z *= 0.125f; v.w *= 0.125f;
        *(float4*)&Ks[r][c] = v;
    }
    __syncthreads();

    // ---- extract Q fragments (hi/lo) into registers ----
    const int qrow = wid * 16 + gr;
    uint32_t qh[8][4], ql[8][4];
    #pragma unroll
    for (int kt = 0; kt < 8; kt++) {
        float f0 = Ks[qrow    ][kt * 8 + tg];
        float f1 = Ks[qrow + 8][kt * 8 + tg];
        float f2 = Ks[qrow    ][kt * 8 + tg + 4];
        float f3 = Ks[qrow + 8][kt * 8 + tg + 4];
        split_tf32(f0, qh[kt][0], ql[kt][0]);
        split_tf32(f1, qh[kt][1], ql[kt][1]);
        split_tf32(f2, qh[kt][2], ql[kt][2]);
        split_tf32(f3, qh[kt][3], ql[kt][3]);
    }
    __syncthreads();

    float o[8][4];
    #pragma unroll
    for (int nt = 0; nt < 8; nt++)
        #pragma unroll
        for (int r = 0; r < 4; r++) o[nt][r] = 0.f;
    float m0 = -1e30f, m1 = -1e30f;
    float l0 = 0.f,    l1 = 0.f;

    for (int j0 = 0; j0 <= q0; j0 += BKV) {
        // ---- load K,V tiles (raw fp32) ----
        #pragma unroll
        for (int it = 0; it < NITER; it++) {
            int idx = it * 128 + tid;
            int r = idx >> 4;
            int c = (idx & 15) * 4;
            size_t tok = (size_t)(j0 + r) * C3_;
            *(float4*)&Ks[r][c] = *(const float4*)(qkv + kbase + tok + c);
            *(float4*)&Vs[r][c] = *(const float4*)(qkv + vbase + tok + c);
        }
        __syncthreads();

        // ---- S = Q K^T  (16 x 64 per warp), 3xTF32 ----
        float s[8][4];
        #pragma unroll
        for (int nt = 0; nt < 8; nt++) {
            #pragma unroll
            for (int r = 0; r < 4; r++) s[nt][r] = 0.f;
            #pragma unroll
            for (int ks = 0; ks < 8; ks++) {
                float b0f = Ks[nt * 8 + gr][ks * 8 + tg];
                float b1f = Ks[nt * 8 + gr][ks * 8 + tg + 4];
                uint32_t bh0, bl0, bh1, bl1;
                split_tf32(b0f, bh0, bl0);
                split_tf32(b1f, bh1, bl1);
                mma_tf32(s[nt], qh[ks][0], qh[ks][1], qh[ks][2], qh[ks][3], bl0, bl1);
                mma_tf32(s[nt], ql[ks][0], ql[ks][1], ql[ks][2], ql[ks][3], bh0, bh1);
                mma_tf32(s[nt], qh[ks][0], qh[ks][1], qh[ks][2], qh[ks][3], bh0, bh1);
            }
        }

        // ---- causal mask (diagonal tile only: j0 == q0) ----
        if (j0 + BKV > q0) {
            const int row0 = q0 + qrow;
            const int row1 = row0 + 8;
            #pragma unroll
            for (int nt = 0; nt < 8; nt++) {
                const int col = j0 + nt * 8 + 2 * tg;
                if (col     > row0) s[nt][0] = -1e30f;
                if (col + 1 > row0) s[nt][1] = -1e30f;
                if (col     > row1) s[nt][2] = -1e30f;
                if (col + 1 > row1) s[nt][3] = -1e30f;
            }
        }

        // ---- online softmax ----
        float t0 = -1e30f, t1 = -1e30f;
        #pragma unroll
        for (int nt = 0; nt < 8; nt++) {
            t0 = fmaxf(t0, fmaxf(s[nt][0], s[nt][1]));
            t1 = fmaxf(t1, fmaxf(s[nt][2], s[nt][3]));
        }
        t0 = fmaxf(t0, __shfl_xor_sync(0xffffffffu, t0, 1));
        t0 = fmaxf(t0, __shfl_xor_sync(0xffffffffu, t0, 2));
        t1 = fmaxf(t1, __shfl_xor_sync(0xffffffffu, t1, 1));
        t1 = fmaxf(t1, __shfl_xor_sync(0xffffffffu, t1, 2));
        const float nm0 = fmaxf(m0, t0);
        const float nm1 = fmaxf(m1, t1);
        const float cr0 = __expf(m0 - nm0);
        const float cr1 = __expf(m1 - nm1);
        m0 = nm0; m1 = nm1;
        l0 *= cr0; l1 *= cr1;
        #pragma unroll
        for (int nt = 0; nt < 8; nt++) {
            o[nt][0] *= cr0; o[nt][1] *= cr0;
            o[nt][2] *= cr1; o[nt][3] *= cr1;
        }
        #pragma unroll
        for (int nt = 0; nt < 8; nt++) {
            s[nt][0] = __expf(s[nt][0] - m0);
            s[nt][1] = __expf(s[nt][1] - m0);
            s[nt][2] = __expf(s[nt][2] - m1);
            s[nt][3] = __expf(s[nt][3] - m1);
            l0 += s[nt][0] + s[nt][1];
            l1 += s[nt][2] + s[nt][3];
        }

        // ---- O += P V : build P A-frag via quad shuffle, 3xTF32 ----
        #pragma unroll
        for (int kt = 0; kt < 8; kt++) {
            const int srcA = (lane & ~3) + (tg >> 1);
            const int srcB = srcA + 2;
            float v0 = __shfl_sync(0xffffffffu, s[kt][0], srcA);
            float v1 = __shfl_sync(0xffffffffu, s[kt][1], srcA);
            float v2 = __shfl_sync(0xffffffffu, s[kt][2], srcA);
            float v3 = __shfl_sync(0xffffffffu, s[kt][3], srcA);
            float w0 = __shfl_sync(0xffffffffu, s[kt][0], srcB);
            float w1 = __shfl_sync(0xffffffffu, s[kt][1], srcB);
            float w2 = __shfl_sync(0xffffffffu, s[kt][2], srcB);
            float w3 = __shfl_sync(0xffffffffu, s[kt][3], srcB);
            const bool odd = (tg & 1);
            float a0f = odd ? v1 : v0;
            float a1f = odd ? v3 : v2;
            float a2f = odd ? w1 : w0;
            float a3f = odd ? w3 : w2;
            uint32_t ah0, al0, ah1, al1, ah2, al2, ah3, al3;
            split_tf32(a0f, ah0, al0);
            split_tf32(a1f, ah1, al1);
            split_tf32(a2f, ah2, al2);
            split_tf32(a3f, ah3, al3);
            #pragma unroll
            for (int nt = 0; nt < 8; nt++) {
                float b0f = Vs[kt * 8 + tg    ][nt * 8 + gr];
                float b1f = Vs[kt * 8 + tg + 4][nt * 8 + gr];
                uint32_t bh0, bl0, bh1, bl1;
                split_tf32(b0f, bh0, bl0);
                split_tf32(b1f, bh1, bl1);
                mma_tf32(o[nt], ah0, ah1, ah2, ah3, bl0, bl1);
                mma_tf32(o[nt], al0, al1, al2, al3, bh0, bh1);
                mma_tf32(o[nt], ah0, ah1, ah2, ah3, bh0, bh1);
            }
        }
        __syncthreads();
    }

    // ---- finalize: reduce l across quad, normalize, write ----
    l0 += __shfl_xor_sync(0xffffffffu, l0, 1);
    l0 += __shfl_xor_sync(0xffffffffu, l0, 2);
    l1 += __shfl_xor_sync(0xffffffffu, l1, 1);
    l1 += __shfl_xor_sync(0xffffffffu, l1, 2);
    const float inv0 = 1.0f / l0;
    const float inv1 = 1.0f / l1;

    const size_t row0 = (size_t)(b * T_ + q0 + qrow);
    #pragma unroll
    for (int nt = 0; nt < 8; nt++) {
        const int col = h * D_ + nt * 8 + 2 * tg;
        *(float2*)(out + row0 * C_ + col)       = make_float2(o[nt][0] * inv0, o[nt][1] * inv0);
        *(float2*)(out + (row0 + 8) * C_ + col) = make_float2(o[nt][2] * inv1, o[nt][3] * inv1);
    }
}

// ---------------------------------------------------------------------------
extern "C" void kernel_launch(void* const* d_in, const int* in_sizes, int n_in,
                              void* d_out, int out_size)
{
    const float* x     = (const float*)d_in[0];   // [B,T,C]
    const float* w_qkv = (const float*)d_in[1];   // [C,3C]
    const float* w_out = (const float*)d_in[2];   // [C,C]
    const float* b_out = (const float*)d_in[3];   // [C]
    float* out = (float*)d_out;                   // [B,T,C]

    float* qkv = nullptr;
    float* att = nullptr;
    cudaGetSymbolAddress((void**)&qkv, g_qkv);
    cudaGetSymbolAddress((void**)&att, g_att);

    // 1) QKV projection: [8192,1024] @ [1024,3072]   (tensor pipe, 3xTF32)
    gemm_tf32x3<<<dim3(C3_ / 128, M_ / 128), 256>>>(x, w_qkv, qkv, nullptr, M_, C3_, C_);

    // 2) Causal flash attention (tensor pipe) -> [B,T,C]
    flash_attn_tc<<<dim3(T_ / 64, H_, B_), 128>>>(qkv, att);

    // 3) Output projection + bias: [8192,1024] @ [1024,1024]   (tensor pipe, 3xTF32)
    gemm_tf32x3<<<dim3(C_ / 128, M_ / 128), 256>>>(att, w_out, out, b_out, M_, C_, C_);
}

// round 15
// speedup vs baseline: 1.8269x; 1.1119x over previous
#include <cuda_runtime.h>
#include <cstdint>

// MultiHeadAttention: B=4, T=2048, C=1024, H=16, D=64
// R14: (1) GEMM forced to 2 CTAs/SM via __launch_bounds__(256,2);
//      (2) flash attention pre-splits K/V hi-lo into smem at load time
//          (dynamic smem, 70KB) -> 3x fewer ALU splits in the mainloop.

#define B_ 4
#define T_ 2048
#define C_ 1024
#define H_ 16
#define D_ 64
#define M_ (B_ * T_)          // 8192
#define C3_ (3 * C_)          // 3072

// Scratch (allocation-free rule: __device__ globals)
__device__ float g_qkv[M_ * C3_];   // ~100.7 MB
__device__ float g_att[M_ * C_];    // ~33.6 MB

// ---------------------------------------------------------------------------
// tf32 helpers
// ---------------------------------------------------------------------------
__device__ __forceinline__ void split_tf32(float x, uint32_t& h, uint32_t& l) {
    uint32_t hi;
    asm("cvt.rna.tf32.f32 %0, %1;" : "=r"(hi) : "f"(x));
    float r = x - __uint_as_float(hi);
    uint32_t lo;
    asm("cvt.rna.tf32.f32 %0, %1;" : "=r"(lo) : "f"(r));
    h = hi; l = lo;
}

__device__ __forceinline__ void mma_tf32(float c[4],
                                         uint32_t a0, uint32_t a1, uint32_t a2, uint32_t a3,
                                         uint32_t b0, uint32_t b1) {
    asm volatile(
        "mma.sync.aligned.m16n8k8.row.col.f32.tf32.tf32.f32 "
        "{%0,%1,%2,%3}, {%4,%5,%6,%7}, {%8,%9}, {%0,%1,%2,%3};\n"
        : "+f"(c[0]), "+f"(c[1]), "+f"(c[2]), "+f"(c[3])
        : "r"(a0), "r"(a1), "r"(a2), "r"(a3), "r"(b0), "r"(b1));
}

__device__ __forceinline__ void cp16(void* smem_ptr, const void* gptr) {
    uint32_t s = (uint32_t)__cvta_generic_to_shared(smem_ptr);
    asm volatile("cp.async.cg.shared.global [%0], [%1], 16;\n" :: "r"(s), "l"(gptr));
}

// ---------------------------------------------------------------------------
// 3xTF32 tensor-core GEMM, cp.async double-buffered, split-at-frag-load.
// A[MxK] * B[KxN] -> C[MxN] (+bias). CTA 128x128x16, 256 thr = 8 warps (2x4),
// warp tile 64x32 (4x4 mma grid). Now 2 CTAs/SM.
// ---------------------------------------------------------------------------
__global__ __launch_bounds__(256, 2) void gemm_tf32x3(
    const float* __restrict__ A, const float* __restrict__ Bm,
    float* __restrict__ Cm, const float* __restrict__ bias,
    int M, int N, int K)
{
    constexpr int BM = 128, BN = 128, BK = 16;
    constexpr int AST = BK + 4;     // 20 floats per A row
    constexpr int BST = BN + 8;     // 136 floats per B row

    __shared__ float Araw[2][BM][AST];   // 20.5 KB
    __shared__ float Braw[2][BK][BST];   // 17.4 KB

    const int tid  = threadIdx.x;
    const int wid  = tid >> 5;
    const int lane = tid & 31;
    const int wm   = wid >> 2;      // 0..1 -> 64-row band
    const int wn   = wid & 3;       // 0..3 -> 32-col band
    const int gr   = lane >> 2;     // 0..7
    const int tg   = lane & 3;      // 0..3

    const int bx = blockIdx.x, by = blockIdx.y;
    const float* Ab = A  + (size_t)by * BM * K;
    const float* Bb = Bm + (size_t)bx * BN;

    const int aRow = tid >> 2;          // 0..63 (and +64)
    const int aCol = (tid & 3) * 4;     // 0,4,8,12
    const int bRow = tid >> 5;          // 0..7 (and +8)
    const int bCol = (tid & 31) * 4;    // 0..124

    const float* aPtr0 = Ab + (size_t)aRow * K + aCol;
    const float* aPtr1 = Ab + (size_t)(aRow + 64) * K + aCol;
    const float* bPtr0 = Bb + (size_t)bRow * N + bCol;
    const float* bPtr1 = Bb + (size_t)(bRow + 8) * N + bCol;

    float acc[4][4][4];
    #pragma unroll
    for (int i = 0; i < 4; i++)
        #pragma unroll
        for (int j = 0; j < 4; j++)
            #pragma unroll
            for (int r = 0; r < 4; r++) acc[i][j][r] = 0.f;

    // prologue: stage tile 0 into buffer 0
    cp16(&Araw[0][aRow     ][aCol], aPtr0);
    cp16(&Araw[0][aRow + 64][aCol], aPtr1);
    cp16(&Braw[0][bRow     ][bCol], bPtr0);
    cp16(&Braw[0][bRow +  8][bCol], bPtr1);
    asm volatile("cp.async.commit_group;\n" ::: "memory");

    int buf = 0;
    for (int k0 = 0; k0 < K; k0 += BK) {
        if (k0 + BK < K) {
            const int nb = buf ^ 1;
            const int kn = k0 + BK;
            cp16(&Araw[nb][aRow     ][aCol], aPtr0 + kn);
            cp16(&Araw[nb][aRow + 64][aCol], aPtr1 + kn);
            cp16(&Braw[nb][bRow     ][bCol], bPtr0 + (size_t)kn * N);
            cp16(&Braw[nb][bRow +  8][bCol], bPtr1 + (size_t)kn * N);
            asm volatile("cp.async.commit_group;\n" ::: "memory");
            asm volatile("cp.async.wait_group 1;\n" ::: "memory");
        } else {
            asm volatile("cp.async.wait_group 0;\n" ::: "memory");
        }
        __syncthreads();

        #pragma unroll
        for (int s = 0; s < 2; s++) {           // two k8 substeps per BK=16
            const int ks = s * 8;
            uint32_t ah[4][4], al_[4][4];
            #pragma unroll
            for (int mi = 0; mi < 4; mi++) {
                const int m = wm * 64 + mi * 16 + gr;
                const int k = ks + tg;
                float f0 = Araw[buf][m    ][k    ];
                float f1 = Araw[buf][m + 8][k    ];
                float f2 = Araw[buf][m    ][k + 4];
                float f3 = Araw[buf][m + 8][k + 4];
                split_tf32(f0, ah[mi][0], al_[mi][0]);
                split_tf32(f1, ah[mi][1], al_[mi][1]);
                split_tf32(f2, ah[mi][2], al_[mi][2]);
                split_tf32(f3, ah[mi][3], al_[mi][3]);
            }
            #pragma unroll
            for (int ni = 0; ni < 4; ni++) {
                const int n  = wn * 32 + ni * 8 + gr;
                const int kb = ks + tg;
                float b0f = Braw[buf][kb    ][n];
                float b1f = Braw[buf][kb + 4][n];
                uint32_t bh0, bl0, bh1, bl1;
                split_tf32(b0f, bh0, bl0);
                split_tf32(b1f, bh1, bl1);
                #pragma unroll
                for (int mi = 0; mi < 4; mi++) {
                    mma_tf32(acc[mi][ni], ah[mi][0], ah[mi][1], ah[mi][2], ah[mi][3], bl0, bl1);
                    mma_tf32(acc[mi][ni], al_[mi][0], al_[mi][1], al_[mi][2], al_[mi][3], bh0, bh1);
                    mma_tf32(acc[mi][ni], ah[mi][0], ah[mi][1], ah[mi][2], ah[mi][3], bh0, bh1);
                }
            }
        }
        __syncthreads();
        buf ^= 1;
    }

    #pragma unroll
    for (int mi = 0; mi < 4; mi++) {
        const int row0 = by * BM + wm * 64 + mi * 16 + gr;
        #pragma unroll
        for (int ni = 0; ni < 4; ni++) {
            const int col = bx * BN + wn * 32 + ni * 8 + tg * 2;
            float bx0 = 0.f, bx1 = 0.f;
            if (bias != nullptr) { bx0 = bias[col]; bx1 = bias[col + 1]; }
            float2 v0 = make_float2(acc[mi][ni][0] + bx0, acc[mi][ni][1] + bx1);
            float2 v1 = make_float2(acc[mi][ni][2] + bx0, acc[mi][ni][3] + bx1);
            *(float2*)(Cm + (size_t)row0 * N + col)       = v0;
            *(float2*)(Cm + (size_t)(row0 + 8) * N + col) = v1;
        }
    }
}

// ---------------------------------------------------------------------------
// Tensor-core flash attention (3xTF32), causal. K/V pre-split hi/lo in smem.
// Grid: (T/64, H, B), 128 threads = 4 warps; warp w owns q rows [w*16, w*16+16).
// Dynamic smem layout (floats):
//   Kh[64][68] @ 0      Kl[64][68] @ 4352
//   Vh[64][72] @ 8704   Vl[64][72] @ 13312      total 17920 floats = 70 KB
// ---------------------------------------------------------------------------
#define KST 68
#define VST 72
#define FA_SMEM_FLOATS (2 * 64 * KST + 2 * 64 * VST)
#define FA_SMEM_BYTES  (FA_SMEM_FLOATS * 4)

__global__ __launch_bounds__(128) void flash_attn_tc(
    const float* __restrict__ qkv, float* __restrict__ out)
{
    constexpr int BKV = 64;
    constexpr int NVEC  = BKV * (D_ / 4);        // 1024
    constexpr int NITER = NVEC / 128;            // 8

    extern __shared__ float sm[];
    float* Kh = sm;                       // [64][KST]
    float* Kl = sm + 64 * KST;            // [64][KST]
    float* Vh = sm + 2 * 64 * KST;        // [64][VST]
    float* Vl = Vh + 64 * VST;            // [64][VST]

    const int tid  = threadIdx.x;
    const int wid  = tid >> 5;
    const int lane = tid & 31;
    const int gr   = lane >> 2;     // 0..7
    const int tg   = lane & 3;      // 0..3

    const int qi = (int)gridDim.x - 1 - (int)blockIdx.x;  // reverse: big CTAs first
    const int h  = blockIdx.y;
    const int b  = blockIdx.z;
    const int q0 = qi * 64;

    const int base  = (b * T_) * C3_ + h * D_;
    const int kbase = base + C_;
    const int vbase = base + 2 * C_;

    // ---- stage raw Q tile (64x64, scaled) into Kh region ----
    #pragma unroll
    for (int it = 0; it < NITER; it++) {
        int idx = it * 128 + tid;
        int r = idx >> 4;                 // D_/4 = 16 float4 per row
        int c = (idx & 15) * 4;
        float4 v = *(const float4*)(qkv + base + (size_t)(q0 + r) * C3_ + c);
        v.x *= 0.125f; v.y *= 0.125f; v.z *= 0.125f; v.w *= 0.125f;
        *(float4*)&Kh[r * KST + c] = v;
    }
    __syncthreads();

    // ---- extract Q fragments (hi/lo) into registers ----
    const int qrow = wid * 16 + gr;
    uint32_t qh[8][4], ql[8][4];
    #pragma unroll
    for (int kt = 0; kt < 8; kt++) {
        float f0 = Kh[(qrow    ) * KST + kt * 8 + tg];
        float f1 = Kh[(qrow + 8) * KST + kt * 8 + tg];
        float f2 = Kh[(qrow    ) * KST + kt * 8 + tg + 4];
        float f3 = Kh[(qrow + 8) * KST + kt * 8 + tg + 4];
        split_tf32(f0, qh[kt][0], ql[kt][0]);
        split_tf32(f1, qh[kt][1], ql[kt][1]);
        split_tf32(f2, qh[kt][2], ql[kt][2]);
        split_tf32(f3, qh[kt][3], ql[kt][3]);
    }
    __syncthreads();

    float o[8][4];
    #pragma unroll
    for (int nt = 0; nt < 8; nt++)
        #pragma unroll
        for (int r = 0; r < 4; r++) o[nt][r] = 0.f;
    float m0 = -1e30f, m1 = -1e30f;
    float l0 = 0.f,    l1 = 0.f;

    for (int j0 = 0; j0 <= q0; j0 += BKV) {
        // ---- load K,V tiles, SPLIT ONCE into hi/lo smem ----
        #pragma unroll
        for (int it = 0; it < NITER; it++) {
            int idx = it * 128 + tid;
            int r = idx >> 4;
            int c = (idx & 15) * 4;
            size_t tok = (size_t)(j0 + r) * C3_;
            float4 kv = *(const float4*)(qkv + kbase + tok + c);
            float4 vv = *(const float4*)(qkv + vbase + tok + c);
            uint32_t hh, ll;
            float4 khv, klv, vhv, vlv;
            split_tf32(kv.x, hh, ll); khv.x = __uint_as_float(hh); klv.x = __uint_as_float(ll);
            split_tf32(kv.y, hh, ll); khv.y = __uint_as_float(hh); klv.y = __uint_as_float(ll);
            split_tf32(kv.z, hh, ll); khv.z = __uint_as_float(hh); klv.z = __uint_as_float(ll);
            split_tf32(kv.w, hh, ll); khv.w = __uint_as_float(hh); klv.w = __uint_as_float(ll);
            split_tf32(vv.x, hh, ll); vhv.x = __uint_as_float(hh); vlv.x = __uint_as_float(ll);
            split_tf32(vv.y, hh, ll); vhv.y = __uint_as_float(hh); vlv.y = __uint_as_float(ll);
            split_tf32(vv.z, hh, ll); vhv.z = __uint_as_float(hh); vlv.z = __uint_as_float(ll);
            split_tf32(vv.w, hh, ll); vhv.w = __uint_as_float(hh); vlv.w = __uint_as_float(ll);
            *(float4*)&Kh[r * KST + c] = khv;
            *(float4*)&Kl[r * KST + c] = klv;
            *(float4*)&Vh[r * VST + c] = vhv;
            *(float4*)&Vl[r * VST + c] = vlv;
        }
        __syncthreads();

        // ---- S = Q K^T  (16 x 64 per warp), 3xTF32, pre-split B frags ----
        float s[8][4];
        #pragma unroll
        for (int nt = 0; nt < 8; nt++) {
            #pragma unroll
            for (int r = 0; r < 4; r++) s[nt][r] = 0.f;
            #pragma unroll
            for (int ks = 0; ks < 8; ks++) {
                const int kr = (nt * 8 + gr) * KST + ks * 8 + tg;
                uint32_t bh0 = __float_as_uint(Kh[kr    ]);
                uint32_t bh1 = __float_as_uint(Kh[kr + 4]);
                uint32_t bl0 = __float_as_uint(Kl[kr    ]);
                uint32_t bl1 = __float_as_uint(Kl[kr + 4]);
                mma_tf32(s[nt], qh[ks][0], qh[ks][1], qh[ks][2], qh[ks][3], bl0, bl1);
                mma_tf32(s[nt], ql[ks][0], ql[ks][1], ql[ks][2], ql[ks][3], bh0, bh1);
                mma_tf32(s[nt], qh[ks][0], qh[ks][1], qh[ks][2], qh[ks][3], bh0, bh1);
            }
        }

        // ---- causal mask (diagonal tile only: j0 == q0) ----
        if (j0 + BKV > q0) {
            const int row0 = q0 + qrow;
            const int row1 = row0 + 8;
            #pragma unroll
            for (int nt = 0; nt < 8; nt++) {
                const int col = j0 + nt * 8 + 2 * tg;
                if (col     > row0) s[nt][0] = -1e30f;
                if (col + 1 > row0) s[nt][1] = -1e30f;
                if (col     > row1) s[nt][2] = -1e30f;
                if (col + 1 > row1) s[nt][3] = -1e30f;
            }
        }

        // ---- online softmax ----
        float t0 = -1e30f, t1 = -1e30f;
        #pragma unroll
        for (int nt = 0; nt < 8; nt++) {
            t0 = fmaxf(t0, fmaxf(s[nt][0], s[nt][1]));
            t1 = fmaxf(t1, fmaxf(s[nt][2], s[nt][3]));
        }
        t0 = fmaxf(t0, __shfl_xor_sync(0xffffffffu, t0, 1));
        t0 = fmaxf(t0, __shfl_xor_sync(0xffffffffu, t0, 2));
        t1 = fmaxf(t1, __shfl_xor_sync(0xffffffffu, t1, 1));
        t1 = fmaxf(t1, __shfl_xor_sync(0xffffffffu, t1, 2));
        const float nm0 = fmaxf(m0, t0);
        const float nm1 = fmaxf(m1, t1);
        const float cr0 = __expf(m0 - nm0);
        const float cr1 = __expf(m1 - nm1);
        m0 = nm0; m1 = nm1;
        l0 *= cr0; l1 *= cr1;
        #pragma unroll
        for (int nt = 0; nt < 8; nt++) {
            o[nt][0] *= cr0; o[nt][1] *= cr0;
            o[nt][2] *= cr1; o[nt][3] *= cr1;
        }
        #pragma unroll
        for (int nt = 0; nt < 8; nt++) {
            s[nt][0] = __expf(s[nt][0] - m0);
            s[nt][1] = __expf(s[nt][1] - m0);
            s[nt][2] = __expf(s[nt][2] - m1);
            s[nt][3] = __expf(s[nt][3] - m1);
            l0 += s[nt][0] + s[nt][1];
            l1 += s[nt][2] + s[nt][3];
        }

        // ---- O += P V : P A-frag via quad shuffle, V frags pre-split ----
        #pragma unroll
        for (int kt = 0; kt < 8; kt++) {
            const int srcA = (lane & ~3) + (tg >> 1);
            const int srcB = srcA + 2;
            float v0 = __shfl_sync(0xffffffffu, s[kt][0], srcA);
            float v1 = __shfl_sync(0xffffffffu, s[kt][1], srcA);
            float v2 = __shfl_sync(0xffffffffu, s[kt][2], srcA);
            float v3 = __shfl_sync(0xffffffffu, s[kt][3], srcA);
            float w0 = __shfl_sync(0xffffffffu, s[kt][0], srcB);
            float w1 = __shfl_sync(0xffffffffu, s[kt][1], srcB);
            float w2 = __shfl_sync(0xffffffffu, s[kt][2], srcB);
            float w3 = __shfl_sync(0xffffffffu, s[kt][3], srcB);
            const bool odd = (tg & 1);
            float a0f = odd ? v1 : v0;
            float a1f = odd ? v3 : v2;
            float a2f = odd ? w1 : w0;
            float a3f = odd ? w3 : w2;
            uint32_t ah0, al0, ah1, al1, ah2, al2, ah3, al3;
            split_tf32(a0f, ah0, al0);
            split_tf32(a1f, ah1, al1);
            split_tf32(a2f, ah2, al2);
            split_tf32(a3f, ah3, al3);
            #pragma unroll
            for (int nt = 0; nt < 8; nt++) {
                const int vr0 = (kt * 8 + tg    ) * VST + nt * 8 + gr;
                const int vr1 = (kt * 8 + tg + 4) * VST + nt * 8 + gr;
                uint32_t bh0 = __float_as_uint(Vh[vr0]);
                uint32_t bh1 = __float_as_uint(Vh[vr1]);
                uint32_t bl0 = __float_as_uint(Vl[vr0]);
                uint32_t bl1 = __float_as_uint(Vl[vr1]);
                mma_tf32(o[nt], ah0, ah1, ah2, ah3, bl0, bl1);
                mma_tf32(o[nt], al0, al1, al2, al3, bh0, bh1);
                mma_tf32(o[nt], ah0, ah1, ah2, ah3, bh0, bh1);
            }
        }
        __syncthreads();
    }

    // ---- finalize: reduce l across quad, normalize, write ----
    l0 += __shfl_xor_sync(0xffffffffu, l0, 1);
    l0 += __shfl_xor_sync(0xffffffffu, l0, 2);
    l1 += __shfl_xor_sync(0xffffffffu, l1, 1);
    l1 += __shfl_xor_sync(0xffffffffu, l1, 2);
    const float inv0 = 1.0f / l0;
    const float inv1 = 1.0f / l1;

    const size_t row0 = (size_t)(b * T_ + q0 + qrow);
    #pragma unroll
    for (int nt = 0; nt < 8; nt++) {
        const int col = h * D_ + nt * 8 + 2 * tg;
        *(float2*)(out + row0 * C_ + col)       = make_float2(o[nt][0] * inv0, o[nt][1] * inv0);
        *(float2*)(out + (row0 + 8) * C_ + col) = make_float2(o[nt][2] * inv1, o[nt][3] * inv1);
    }
}

// ---------------------------------------------------------------------------
extern "C" void kernel_launch(void* const* d_in, const int* in_sizes, int n_in,
                              void* d_out, int out_size)
{
    const float* x     = (const float*)d_in[0];   // [B,T,C]
    const float* w_qkv = (const float*)d_in[1];   // [C,3C]
    const float* w_out = (const float*)d_in[2];   // [C,C]
    const float* b_out = (const float*)d_in[3];   // [C]
    float* out = (float*)d_out;                   // [B,T,C]

    float* qkv = nullptr;
    float* att = nullptr;
    cudaGetSymbolAddress((void**)&qkv, g_qkv);
    cudaGetSymbolAddress((void**)&att, g_att);

    // allow 70KB dynamic smem for the flash kernel (set before capture; persists)
    static bool attr_done = false;
    if (!attr_done) {
        cudaFuncSetAttribute(flash_attn_tc,
                             cudaFuncAttributeMaxDynamicSharedMemorySize, FA_SMEM_BYTES);
        attr_done = true;
    }

    // 1) QKV projection: [8192,1024] @ [1024,3072]   (tensor pipe, 3xTF32)
    gemm_tf32x3<<<dim3(C3_ / 128, M_ / 128), 256>>>(x, w_qkv, qkv, nullptr, M_, C3_, C_);

    // 2) Causal flash attention (tensor pipe) -> [B,T,C]
    flash_attn_tc<<<dim3(T_ / 64, H_, B_), 128, FA_SMEM_BYTES>>>(qkv, att);

    // 3) Output projection + bias: [8192,1024] @ [1024,1024]   (tensor pipe, 3xTF32)
    gemm_tf32x3<<<dim3(C_ / 128, M_ / 128), 256>>>(att, w_out, out, b_out, M_, C_, C_);
}

// round 17
// speedup vs baseline: 2.4460x; 1.3389x over previous
#include <cuda_runtime.h>
#include <cuda_bf16.h>
#include <cstdint>

// MultiHeadAttention: B=4, T=2048, C=1024, H=16, D=64
// R16: tcgen05 unavailable in this toolchain (ptxas targets sm_103 w/o 'a'
//      features) -> stay on mma.sync. Projection GEMMs converted to 3-term
//      bf16x2 m16n8k16 (2x FLOP/instr vs tf32 k8). Flash attention identical
//      to the verified R14 kernel.

#define B_ 4
#define T_ 2048
#define C_ 1024
#define H_ 16
#define D_ 64
#define M_ (B_ * T_)          // 8192
#define C3_ (3 * C_)          // 3072

// Scratch (allocation-free rule: __device__ globals)
__device__ float g_qkv[M_ * C3_];     // ~100.7 MB
__device__ float g_att[M_ * C_];      // ~33.6 MB
__device__ float g_wqkvT[C3_ * C_];   // 12 MB   [N=3072][K=1024]
__device__ float g_woutT[C_ * C_];    // 4 MB    [N=1024][K=1024]

// ---------------------------------------------------------------------------
// numeric helpers
// ---------------------------------------------------------------------------
// split pair (x0 = even k, x1 = odd k) into packed bf16x2 hi + lo words.
// Packing: lower 16 bits = even-k element (mma expects low k in low half).
__device__ __forceinline__ void split_pair_bf16(float x0, float x1,
                                                uint32_t& hp, uint32_t& lp) {
    asm("cvt.rn.bf16x2.f32 %0, %1, %2;" : "=r"(hp) : "f"(x1), "f"(x0));
    // bf16 -> f32 is exact: bits << 16
    float h0 = __uint_as_float(hp << 16);
    float h1 = __uint_as_float(hp & 0xffff0000u);
    float l0 = x0 - h0;
    float l1 = x1 - h1;
    asm("cvt.rn.bf16x2.f32 %0, %1, %2;" : "=r"(lp) : "f"(l1), "f"(l0));
}

__device__ __forceinline__ void mma_bf16(float c[4],
                                         uint32_t a0, uint32_t a1, uint32_t a2, uint32_t a3,
                                         uint32_t b0, uint32_t b1) {
    asm volatile(
        "mma.sync.aligned.m16n8k16.row.col.f32.bf16.bf16.f32 "
        "{%0,%1,%2,%3}, {%4,%5,%6,%7}, {%8,%9}, {%0,%1,%2,%3};\n"
        : "+f"(c[0]), "+f"(c[1]), "+f"(c[2]), "+f"(c[3])
        : "r"(a0), "r"(a1), "r"(a2), "r"(a3), "r"(b0), "r"(b1));
}

// tf32 helpers (flash attention, unchanged from R14)
__device__ __forceinline__ void split_tf32(float x, uint32_t& h, uint32_t& l) {
    uint32_t hi;
    asm("cvt.rna.tf32.f32 %0, %1;" : "=r"(hi) : "f"(x));
    float r = x - __uint_as_float(hi);
    uint32_t lo;
    asm("cvt.rna.tf32.f32 %0, %1;" : "=r"(lo) : "f"(r));
    h = hi; l = lo;
}

__device__ __forceinline__ void mma_tf32(float c[4],
                                         uint32_t a0, uint32_t a1, uint32_t a2, uint32_t a3,
                                         uint32_t b0, uint32_t b1) {
    asm volatile(
        "mma.sync.aligned.m16n8k8.row.col.f32.tf32.tf32.f32 "
        "{%0,%1,%2,%3}, {%4,%5,%6,%7}, {%8,%9}, {%0,%1,%2,%3};\n"
        : "+f"(c[0]), "+f"(c[1]), "+f"(c[2]), "+f"(c[3])
        : "r"(a0), "r"(a1), "r"(a2), "r"(a3), "r"(b0), "r"(b1));
}

// ---------------------------------------------------------------------------
// Weight transpose: src[K][N] -> dst[N][K]
// ---------------------------------------------------------------------------
__global__ __launch_bounds__(256) void transposeW(
    const float* __restrict__ src, float* __restrict__ dst, int K, int N)
{
    __shared__ float t[32][33];
    const int n0 = blockIdx.x * 32, k0 = blockIdx.y * 32;
    const int x = threadIdx.x, y = threadIdx.y;
    #pragma unroll
    for (int i = 0; i < 32; i += 8)
        t[y + i][x] = src[(size_t)(k0 + y + i) * N + n0 + x];
    __syncthreads();
    #pragma unroll
    for (int i = 0; i < 32; i += 8)
        dst[(size_t)(n0 + y + i) * K + k0 + x] = t[x][y + i];
}

// ---------------------------------------------------------------------------
// 3-term bf16x2 tensor-core GEMM: C[MxN] = A[MxK] * Bt[NxK]^T (+bias)
// CTA 128x128x32, 256 thr = 8 warps (2x4), warp tile 64x32, m16n8k16 mma.
// Operands staged as packed bf16x2 (hi & lo), K-major, row stride 20 words
// (16 data + 4 pad: frag-load banks 20*gr+tg all distinct). Double-buffered.
// ---------------------------------------------------------------------------
static constexpr int AST2 = 20;          // uint32 words per operand row
static constexpr int OPW  = 128 * AST2;  // 2560 words per operand-half tile
static constexpr int STGW = 4 * OPW;     // Ah, Al, Bh, Bl
static constexpr int GEMM_SMEM = 2 * STGW * 4;   // 81920 B

__device__ __forceinline__ void cvt_store8(uint32_t* Hp, uint32_t* Lp, int widx,
                                           float4 v0, float4 v1) {
    uint32_t hw0, lw0, hw1, lw1, hw2, lw2, hw3, lw3;
    split_pair_bf16(v0.x, v0.y, hw0, lw0);
    split_pair_bf16(v0.z, v0.w, hw1, lw1);
    split_pair_bf16(v1.x, v1.y, hw2, lw2);
    split_pair_bf16(v1.z, v1.w, hw3, lw3);
    *(uint4*)(Hp + widx) = make_uint4(hw0, hw1, hw2, hw3);
    *(uint4*)(Lp + widx) = make_uint4(lw0, lw1, lw2, lw3);
}

__global__ __launch_bounds__(256, 2) void gemm_bf16x3(
    const float* __restrict__ A, const float* __restrict__ Bt,
    float* __restrict__ Cm, const float* __restrict__ bias, int N, int K)
{
    extern __shared__ uint32_t smw[];

    const int tid  = threadIdx.x;
    const int wid  = tid >> 5;
    const int lane = tid & 31;
    const int wm   = wid >> 2;      // 0..1 -> 64-row band
    const int wn   = wid & 3;       // 0..3 -> 32-col band
    const int gr   = lane >> 2;     // 0..7
    const int tg   = lane & 3;      // 0..3

    const float* Ab = A  + (size_t)blockIdx.y * 128 * K;
    const float* Bb = Bt + (size_t)blockIdx.x * 128 * K;

    // staging mapping: thread -> rows r, r+64; 8-float chunk cq*8 within tile
    const int r  = tid >> 2;        // 0..63
    const int cq = tid & 3;         // 0..3
    const float* aP0 = Ab + (size_t)r * K + cq * 8;
    const float* aP1 = Ab + (size_t)(r + 64) * K + cq * 8;
    const float* bP0 = Bb + (size_t)r * K + cq * 8;
    const float* bP1 = Bb + (size_t)(r + 64) * K + cq * 8;
    const int w0 = r * AST2 + cq * 4;          // word offset, row r
    const int w1 = (r + 64) * AST2 + cq * 4;   // word offset, row r+64

    float acc[4][4][4];
    #pragma unroll
    for (int i = 0; i < 4; i++)
        #pragma unroll
        for (int j = 0; j < 4; j++)
            #pragma unroll
            for (int q = 0; q < 4; q++) acc[i][j][q] = 0.f;

    const int nT = K >> 5;   // K/32 tiles

    // prologue: stage tile 0 into buffer 0
    {
        float4 v0 = *(const float4*)(aP0);
        float4 v1 = *(const float4*)(aP0 + 4);
        float4 v2 = *(const float4*)(aP1);
        float4 v3 = *(const float4*)(aP1 + 4);
        cvt_store8(smw, smw + OPW, w0, v0, v1);
        cvt_store8(smw, smw + OPW, w1, v2, v3);
        v0 = *(const float4*)(bP0);
        v1 = *(const float4*)(bP0 + 4);
        v2 = *(const float4*)(bP1);
        v3 = *(const float4*)(bP1 + 4);
        cvt_store8(smw + 2 * OPW, smw + 3 * OPW, w0, v0, v1);
        cvt_store8(smw + 2 * OPW, smw + 3 * OPW, w1, v2, v3);
    }
    __syncthreads();

    for (int it = 0; it < nT; it++) {
        const uint32_t* cb = smw + (it & 1) * STGW;
        uint32_t* nb = smw + ((it & 1) ^ 1) * STGW;
        const bool have = (it + 1 < nT);
        const int kn = (it + 1) << 5;

        float4 p0, p1, p2, p3;
        if (have) {
            p0 = *(const float4*)(aP0 + kn);
            p1 = *(const float4*)(aP0 + kn + 4);
            p2 = *(const float4*)(aP1 + kn);
            p3 = *(const float4*)(aP1 + kn + 4);
        }

        #pragma unroll
        for (int kc = 0; kc < 2; kc++) {       // two k16 chunks per BK=32
            const int kcb = kc * 8;
            const uint32_t* Ah = cb;
            const uint32_t* Al = cb + OPW;
            const uint32_t* Bh = cb + 2 * OPW;
            const uint32_t* Bl = cb + 3 * OPW;

            uint32_t ah[4][4], al[4][4];
            #pragma unroll
            for (int mi = 0; mi < 4; mi++) {
                const int m  = wm * 64 + mi * 16 + gr;
                const int i0 = m * AST2 + kcb + tg;
                ah[mi][0] = Ah[i0];
                ah[mi][1] = Ah[i0 + 8 * AST2];
                ah[mi][2] = Ah[i0 + 4];
                ah[mi][3] = Ah[i0 + 8 * AST2 + 4];
                al[mi][0] = Al[i0];
                al[mi][1] = Al[i0 + 8 * AST2];
                al[mi][2] = Al[i0 + 4];
                al[mi][3] = Al[i0 + 8 * AST2 + 4];
            }
            #pragma unroll
            for (int ni = 0; ni < 4; ni++) {
                const int n  = wn * 32 + ni * 8 + gr;
                const int j0 = n * AST2 + kcb + tg;
                uint32_t bh0 = Bh[j0], bh1 = Bh[j0 + 4];
                uint32_t bl0 = Bl[j0], bl1 = Bl[j0 + 4];
                #pragma unroll
                for (int mi = 0; mi < 4; mi++) {
                    mma_bf16(acc[mi][ni], ah[mi][0], ah[mi][1], ah[mi][2], ah[mi][3], bl0, bl1);
                    mma_bf16(acc[mi][ni], al[mi][0], al[mi][1], al[mi][2], al[mi][3], bh0, bh1);
                    mma_bf16(acc[mi][ni], ah[mi][0], ah[mi][1], ah[mi][2], ah[mi][3], bh0, bh1);
                }
            }

            // interleave staging of next tile between the two chunks
            if (kc == 0 && have) {
                cvt_store8(nb, nb + OPW, w0, p0, p1);
                cvt_store8(nb, nb + OPW, w1, p2, p3);
                p0 = *(const float4*)(bP0 + kn);
                p1 = *(const float4*)(bP0 + kn + 4);
                p2 = *(const float4*)(bP1 + kn);
                p3 = *(const float4*)(bP1 + kn + 4);
            }
        }
        if (have) {
            cvt_store8(nb + 2 * OPW, nb + 3 * OPW, w0, p0, p1);
            cvt_store8(nb + 2 * OPW, nb + 3 * OPW, w1, p2, p3);
        }
        __syncthreads();
    }

    // epilogue (C-frag layout identical to k8 mma)
    #pragma unroll
    for (int mi = 0; mi < 4; mi++) {
        const int row0 = blockIdx.y * 128 + wm * 64 + mi * 16 + gr;
        #pragma unroll
        for (int ni = 0; ni < 4; ni++) {
            const int col = blockIdx.x * 128 + wn * 32 + ni * 8 + tg * 2;
            float bx0 = 0.f, bx1 = 0.f;
            if (bias != nullptr) { bx0 = bias[col]; bx1 = bias[col + 1]; }
            float2 v0 = make_float2(acc[mi][ni][0] + bx0, acc[mi][ni][1] + bx1);
            float2 v1 = make_float2(acc[mi][ni][2] + bx0, acc[mi][ni][3] + bx1);
            *(float2*)(Cm + (size_t)row0 * N + col)       = v0;
            *(float2*)(Cm + (size_t)(row0 + 8) * N + col) = v1;
        }
    }
}

// ---------------------------------------------------------------------------
// Tensor-core flash attention (3xTF32), causal. IDENTICAL to verified R14.
// ---------------------------------------------------------------------------
#define KST 68
#define VST 72
#define FA_SMEM_FLOATS (2 * 64 * KST + 2 * 64 * VST)
#define FA_SMEM_BYTES  (FA_SMEM_FLOATS * 4)

__global__ __launch_bounds__(128) void flash_attn_tc(
    const float* __restrict__ qkv, float* __restrict__ out)
{
    constexpr int BKV = 64;
    constexpr int NVEC  = BKV * (D_ / 4);        // 1024
    constexpr int NITER = NVEC / 128;            // 8

    extern __shared__ float sm[];
    float* Kh = sm;
    float* Kl = sm + 64 * KST;
    float* Vh = sm + 2 * 64 * KST;
    float* Vl = Vh + 64 * VST;

    const int tid  = threadIdx.x;
    const int wid  = tid >> 5;
    const int lane = tid & 31;
    const int gr   = lane >> 2;
    const int tg   = lane & 3;

    const int qi = (int)gridDim.x - 1 - (int)blockIdx.x;
    const int h  = blockIdx.y;
    const int b  = blockIdx.z;
    const int q0 = qi * 64;

    const int base  = (b * T_) * C3_ + h * D_;
    const int kbase = base + C_;
    const int vbase = base + 2 * C_;

    #pragma unroll
    for (int it = 0; it < NITER; it++) {
        int idx = it * 128 + tid;
        int r = idx >> 4;
        int c = (idx & 15) * 4;
        float4 v = *(const float4*)(qkv + base + (size_t)(q0 + r) * C3_ + c);
        v.x *= 0.125f; v.y *= 0.125f; v.z *= 0.125f; v.w *= 0.125f;
        *(float4*)&Kh[r * KST + c] = v;
    }
    __syncthreads();

    const int qrow = wid * 16 + gr;
    uint32_t qh[8][4], ql[8][4];
    #pragma unroll
    for (int kt = 0; kt < 8; kt++) {
        float f0 = Kh[(qrow    ) * KST + kt * 8 + tg];
        float f1 = Kh[(qrow + 8) * KST + kt * 8 + tg];
        float f2 = Kh[(qrow    ) * KST + kt * 8 + tg + 4];
        float f3 = Kh[(qrow + 8) * KST + kt * 8 + tg + 4];
        split_tf32(f0, qh[kt][0], ql[kt][0]);
        split_tf32(f1, qh[kt][1], ql[kt][1]);
        split_tf32(f2, qh[kt][2], ql[kt][2]);
        split_tf32(f3, qh[kt][3], ql[kt][3]);
    }
    __syncthreads();

    float o[8][4];
    #pragma unroll
    for (int nt = 0; nt < 8; nt++)
        #pragma unroll
        for (int r = 0; r < 4; r++) o[nt][r] = 0.f;
    float m0 = -1e30f, m1 = -1e30f;
    float l0 = 0.f,    l1 = 0.f;

    for (int j0 = 0; j0 <= q0; j0 += BKV) {
        #pragma unroll
        for (int it = 0; it < NITER; it++) {
            int idx = it * 128 + tid;
            int r = idx >> 4;
            int c = (idx & 15) * 4;
            size_t tok = (size_t)(j0 + r) * C3_;
            float4 kv = *(const float4*)(qkv + kbase + tok + c);
            float4 vv = *(const float4*)(qkv + vbase + tok + c);
            uint32_t hh, ll;
            float4 khv, klv, vhv, vlv;
            split_tf32(kv.x, hh, ll); khv.x = __uint_as_float(hh); klv.x = __uint_as_float(ll);
            split_tf32(kv.y, hh, ll); khv.y = __uint_as_float(hh); klv.y = __uint_as_float(ll);
            split_tf32(kv.z, hh, ll); khv.z = __uint_as_float(hh); klv.z = __uint_as_float(ll);
            split_tf32(kv.w, hh, ll); khv.w = __uint_as_float(hh); klv.w = __uint_as_float(ll);
            split_tf32(vv.x, hh, ll); vhv.x = __uint_as_float(hh); vlv.x = __uint_as_float(ll);
            split_tf32(vv.y, hh, ll); vhv.y = __uint_as_float(hh); vlv.y = __uint_as_float(ll);
            split_tf32(vv.z, hh, ll); vhv.z = __uint_as_float(hh); vlv.z = __uint_as_float(ll);
            split_tf32(vv.w, hh, ll); vhv.w = __uint_as_float(hh); vlv.w = __uint_as_float(ll);
            *(float4*)&Kh[r * KST + c] = khv;
            *(float4*)&Kl[r * KST + c] = klv;
            *(float4*)&Vh[r * VST + c] = vhv;
            *(float4*)&Vl[r * VST + c] = vlv;
        }
        __syncthreads();

        float s[8][4];
        #pragma unroll
        for (int nt = 0; nt < 8; nt++) {
            #pragma unroll
            for (int r = 0; r < 4; r++) s[nt][r] = 0.f;
            #pragma unroll
            for (int ks = 0; ks < 8; ks++) {
                const int kr = (nt * 8 + gr) * KST + ks * 8 + tg;
                uint32_t bh0 = __float_as_uint(Kh[kr    ]);
                uint32_t bh1 = __float_as_uint(Kh[kr + 4]);
                uint32_t bl0 = __float_as_uint(Kl[kr    ]);
                uint32_t bl1 = __float_as_uint(Kl[kr + 4]);
                mma_tf32(s[nt], qh[ks][0], qh[ks][1], qh[ks][2], qh[ks][3], bl0, bl1);
                mma_tf32(s[nt], ql[ks][0], ql[ks][1], ql[ks][2], ql[ks][3], bh0, bh1);
                mma_tf32(s[nt], qh[ks][0], qh[ks][1], qh[ks][2], qh[ks][3], bh0, bh1);
            }
        }

        if (j0 + BKV > q0) {
            const int row0 = q0 + qrow;
            const int row1 = row0 + 8;
            #pragma unroll
            for (int nt = 0; nt < 8; nt++) {
                const int col = j0 + nt * 8 + 2 * tg;
                if (col     > row0) s[nt][0] = -1e30f;
                if (col + 1 > row0) s[nt][1] = -1e30f;
                if (col     > row1) s[nt][2] = -1e30f;
                if (col + 1 > row1) s[nt][3] = -1e30f;
            }
        }

        float t0 = -1e30f, t1 = -1e30f;
        #pragma unroll
        for (int nt = 0; nt < 8; nt++) {
            t0 = fmaxf(t0, fmaxf(s[nt][0], s[nt][1]));
            t1 = fmaxf(t1, fmaxf(s[nt][2], s[nt][3]));
        }
        t0 = fmaxf(t0, __shfl_xor_sync(0xffffffffu, t0, 1));
        t0 = fmaxf(t0, __shfl_xor_sync(0xffffffffu, t0, 2));
        t1 = fmaxf(t1, __shfl_xor_sync(0xffffffffu, t1, 1));
        t1 = fmaxf(t1, __shfl_xor_sync(0xffffffffu, t1, 2));
        const float nm0 = fmaxf(m0, t0);
        const float nm1 = fmaxf(m1, t1);
        const float cr0 = __expf(m0 - nm0);
        const float cr1 = __expf(m1 - nm1);
        m0 = nm0; m1 = nm1;
        l0 *= cr0; l1 *= cr1;
        #pragma unroll
        for (int nt = 0; nt < 8; nt++) {
            o[nt][0] *= cr0; o[nt][1] *= cr0;
            o[nt][2] *= cr1; o[nt][3] *= cr1;
        }
        #pragma unroll
        for (int nt = 0; nt < 8; nt++) {
            s[nt][0] = __expf(s[nt][0] - m0);
            s[nt][1] = __expf(s[nt][1] - m0);
            s[nt][2] = __expf(s[nt][2] - m1);
            s[nt][3] = __expf(s[nt][3] - m1);
            l0 += s[nt][0] + s[nt][1];
            l1 += s[nt][2] + s[nt][3];
        }

        #pragma unroll
        for (int kt = 0; kt < 8; kt++) {
            const int srcA = (lane & ~3) + (tg >> 1);
            const int srcB = srcA + 2;
            float v0 = __shfl_sync(0xffffffffu, s[kt][0], srcA);
            float v1 = __shfl_sync(0xffffffffu, s[kt][1], srcA);
            float v2 = __shfl_sync(0xffffffffu, s[kt][2], srcA);
            float v3 = __shfl_sync(0xffffffffu, s[kt][3], srcA);
            float w0 = __shfl_sync(0xffffffffu, s[kt][0], srcB);
            float w1 = __shfl_sync(0xffffffffu, s[kt][1], srcB);
            float w2 = __shfl_sync(0xffffffffu, s[kt][2], srcB);
            float w3 = __shfl_sync(0xffffffffu, s[kt][3], srcB);
            const bool odd = (tg & 1);
            float a0f = odd ? v1 : v0;
            float a1f = odd ? v3 : v2;
            float a2f = odd ? w1 : w0;
            float a3f = odd ? w3 : w2;
            uint32_t ah0, al0, ah1, al1, ah2, al2, ah3, al3;
            split_tf32(a0f, ah0, al0);
            split_tf32(a1f, ah1, al1);
            split_tf32(a2f, ah2, al2);
            split_tf32(a3f, ah3, al3);
            #pragma unroll
            for (int nt = 0; nt < 8; nt++) {
                const int vr0 = (kt * 8 + tg    ) * VST + nt * 8 + gr;
                const int vr1 = (kt * 8 + tg + 4) * VST + nt * 8 + gr;
                uint32_t bh0 = __float_as_uint(Vh[vr0]);
                uint32_t bh1 = __float_as_uint(Vh[vr1]);
                uint32_t bl0 = __float_as_uint(Vl[vr0]);
                uint32_t bl1 = __float_as_uint(Vl[vr1]);
                mma_tf32(o[nt], ah0, ah1, ah2, ah3, bl0, bl1);
                mma_tf32(o[nt], al0, al1, al2, al3, bh0, bh1);
                mma_tf32(o[nt], ah0, ah1, ah2, ah3, bh0, bh1);
            }
        }
        __syncthreads();
    }

    l0 += __shfl_xor_sync(0xffffffffu, l0, 1);
    l0 += __shfl_xor_sync(0xffffffffu, l0, 2);
    l1 += __shfl_xor_sync(0xffffffffu, l1, 1);
    l1 += __shfl_xor_sync(0xffffffffu, l1, 2);
    const float inv0 = 1.0f / l0;
    const float inv1 = 1.0f / l1;

    const size_t row0 = (size_t)(b * T_ + q0 + qrow);
    #pragma unroll
    for (int nt = 0; nt < 8; nt++) {
        const int col = h * D_ + nt * 8 + 2 * tg;
        *(float2*)(out + row0 * C_ + col)       = make_float2(o[nt][0] * inv0, o[nt][1] * inv0);
        *(float2*)(out + (row0 + 8) * C_ + col) = make_float2(o[nt][2] * inv1, o[nt][3] * inv1);
    }
}

// ---------------------------------------------------------------------------
extern "C" void kernel_launch(void* const* d_in, const int* in_sizes, int n_in,
                              void* d_out, int out_size)
{
    const float* x     = (const float*)d_in[0];   // [B,T,C]
    const float* w_qkv = (const float*)d_in[1];   // [C,3C]
    const float* w_out = (const float*)d_in[2];   // [C,C]
    const float* b_out = (const float*)d_in[3];   // [C]
    float* out = (float*)d_out;                   // [B,T,C]

    float *qkv = nullptr, *att = nullptr, *wqkvT = nullptr, *woutT = nullptr;
    cudaGetSymbolAddress((void**)&qkv,   g_qkv);
    cudaGetSymbolAddress((void**)&att,   g_att);
    cudaGetSymbolAddress((void**)&wqkvT, g_wqkvT);
    cudaGetSymbolAddress((void**)&woutT, g_woutT);

    static bool attr_done = false;
    if (!attr_done) {
        cudaFuncSetAttribute(flash_attn_tc,
                             cudaFuncAttributeMaxDynamicSharedMemorySize, FA_SMEM_BYTES);
        cudaFuncSetAttribute(gemm_bf16x3,
                             cudaFuncAttributeMaxDynamicSharedMemorySize, GEMM_SMEM);
        attr_done = true;
    }

    // 0) transpose weights to [N][K]
    transposeW<<<dim3(C3_ / 32, C_ / 32), dim3(32, 8)>>>(w_qkv, wqkvT, C_, C3_);
    transposeW<<<dim3(C_ / 32, C_ / 32), dim3(32, 8)>>>(w_out, woutT, C_, C_);

    // 1) QKV projection (bf16x2 3-term, m16n8k16): [8192,1024] @ [1024,3072]
    gemm_bf16x3<<<dim3(C3_ / 128, M_ / 128), 256, GEMM_SMEM>>>(x, wqkvT, qkv, nullptr, C3_, C_);

    // 2) Causal flash attention (3xTF32) -> [B,T,C]
    flash_attn_tc<<<dim3(T_ / 64, H_, B_), 128, FA_SMEM_BYTES>>>(qkv, att);

    // 3) Output projection + bias: [8192,1024] @ [1024,1024]
    gemm_bf16x3<<<dim3(C_ / 128, M_ / 128), 256, GEMM_SMEM>>>(att, woutT, out, b_out, C_, C_);
}